// round 15
// baseline (speedup 1.0000x reference)
#include <cuda_runtime.h>
#include <cuda_bf16.h>

// HopfieldTSP — FINAL (revert to best-measured config, R5).
//
// Math: x_1000 = sign(w @ x0). With w = 2*diag(rowsum) - adj + diag(adj_ii)
// and adj >= 0, x1 = sign(w@x0) is a provable fixed point of the iteration
// (margin rowsum_i ~ 4096 >> fp32 rounding), so 1000 iterations collapse to
// ONE fused pass: rowsum_i and dot_i = (adj@x0)_i computed together, then
//   s_i = (2*rowsum_i + adj_ii)*x0_i - dot_i ;  out_i = sign(s_i).
//
// Performance: the 268MB single-pass read runs at ~5.76TB/s — the measured
// chip read ceiling for this pattern, reproduced across LDG (all cache-ops),
// TMA bulk pipelines, and cp.async with 118KB/SM in flight (R1-R14). This
// kernel runs at ~99% of that ceiling (47.4us vs 46.7us ideal). Shape:
// 256-thread blocks, one full row per warp (no barriers, no smem), adj via
// __ldcs streaming, x via __ldg (hot in L1), grid 1024 = one wave @ 8 blk/SM.

#define N_CITIES 8192
#define THREADS 256
#define ROWS_PER_BLOCK (THREADS / 32)   // 8
#define ROW4 (N_CITIES / 4)             // 2048 float4 per row

__global__ void __launch_bounds__(THREADS, 8)
hopfield_fused_kernel(const float* __restrict__ adj,
                      const float* __restrict__ x,
                      float* __restrict__ out) {
    const int warp = threadIdx.x >> 5;
    const int lane = threadIdx.x & 31;
    const int row  = blockIdx.x * ROWS_PER_BLOCK + warp;

    const float4* arow = reinterpret_cast<const float4*>(adj + (size_t)row * N_CITIES);
    const float4* x4   = reinterpret_cast<const float4*>(x);

    // 64 trips per lane. adj: streaming (evict-first) so it never evicts x
    // from L1; x: read-only path, hot in L1 after first touch.
    float rs = 0.0f, dot = 0.0f;
    #pragma unroll 2
    for (int j = lane; j < ROW4; j += 32) {
        float4 a  = __ldcs(&arow[j]);
        float4 xv = __ldg(&x4[j]);
        rs  += (a.x + a.y) + (a.z + a.w);
        dot += a.x * xv.x + a.y * xv.y + a.z * xv.z + a.w * xv.w;
    }

    #pragma unroll
    for (int o = 16; o > 0; o >>= 1) {
        rs  += __shfl_xor_sync(0xFFFFFFFFu, rs, o);
        dot += __shfl_xor_sync(0xFFFFFFFFu, dot, o);
    }

    if (lane == 0) {
        float aii = __ldg(adj + (size_t)row * N_CITIES + row);
        float xi  = __ldg(x + row);
        float s   = (2.0f * rs + aii) * xi - dot;
        out[row] = (s > 0.0f) ? 1.0f : ((s < 0.0f) ? -1.0f : 0.0f);
    }
}

extern "C" void kernel_launch(void* const* d_in, const int* in_sizes, int n_in,
                              void* d_out, int out_size) {
    const float* adj = (const float*)d_in[0];   // [8192, 8192] fp32 row-major
    const float* x   = (const float*)d_in[1];   // [8192] fp32
    float* out       = (float*)d_out;           // [8192] fp32

    hopfield_fused_kernel<<<N_CITIES / ROWS_PER_BLOCK, THREADS>>>(adj, x, out);
}

// round 16
// speedup vs baseline: 1.0012x; 1.0012x over previous
#include <cuda_runtime.h>
#include <cuda_bf16.h>

// HopfieldTSP — FINAL. Best-measured configuration of the session (R2:
// 47.20us kernel, 5.79TB/s — highest HBM of any variant).
//
// Math: x_1000 = sign(w @ x0). With w = 2*diag(rowsum) - adj (off-diag) and
// adj >= 0, x1 = sign(w@x0) is a provable fixed point (margin rowsum_i ~ 4096
// >> fp32 rounding), so 1000 iterations collapse to ONE fused pass computing
// rowsum_i and dot_i = (adj@x0)_i together:
//   s_i = (2*rowsum_i + adj_ii)*x0_i - dot_i ;  out_i = sign(s_i).
//
// Performance: the 268MB single-pass read runs at the measured chip read
// ceiling (~5.7-5.8TB/s), reproduced across LDG (all 4 cache-ops), TMA bulk
// pipelines, and cp.async with 118KB/SM in flight (R1-R15). Inter-hold noise
// is +-2-3us and exceeds all remaining variant differences. This shape:
// 512-thread blocks (16 rows), x staged once in 32KB smem (zero per-iter L1
// x-traffic — adj owns L1tex), 4 blocks/SM via launch_bounds (regs<=32),
// grid 512 = one wave.

#define N_CITIES 8192
#define ROWS_PER_BLOCK 16
#define THREADS (ROWS_PER_BLOCK * 32)   // 512

__global__ void __launch_bounds__(THREADS, 4)
hopfield_fused_kernel(const float* __restrict__ adj,
                      const float* __restrict__ x,
                      float* __restrict__ out) {
    __shared__ float xs[N_CITIES];  // 32 KB, staged once, shared by 16 warps

    const float4* x4 = reinterpret_cast<const float4*>(x);
    float4* xs4 = reinterpret_cast<float4*>(xs);
    #pragma unroll
    for (int i = threadIdx.x; i < N_CITIES / 4; i += THREADS) {
        xs4[i] = x4[i];
    }
    __syncthreads();

    const int warp = threadIdx.x >> 5;
    const int lane = threadIdx.x & 31;
    const int row  = blockIdx.x * ROWS_PER_BLOCK + warp;

    const float4* arow = reinterpret_cast<const float4*>(adj + (size_t)row * N_CITIES);

    // 64 trips of LDG.128 per lane; unroll 4 keeps regs <= 32 (no spills)
    // while giving MLP=4 per warp (64 warps/SM -> ample outstanding bytes).
    float rs = 0.0f;   // rowsum partial
    float dot = 0.0f;  // (adj @ x0) partial
    #pragma unroll 4
    for (int j = lane; j < N_CITIES / 4; j += 32) {
        float4 a  = arow[j];
        float4 xv = xs4[j];
        rs  += (a.x + a.y) + (a.z + a.w);
        dot += a.x * xv.x + a.y * xv.y + a.z * xv.z + a.w * xv.w;
    }

    #pragma unroll
    for (int o = 16; o > 0; o >>= 1) {
        rs  += __shfl_xor_sync(0xFFFFFFFFu, rs, o);
        dot += __shfl_xor_sync(0xFFFFFFFFu, dot, o);
    }

    if (lane == 0) {
        float aii = __ldg(adj + (size_t)row * N_CITIES + row);
        float xi  = xs[row];
        float s   = (2.0f * rs + aii) * xi - dot;
        out[row] = (s > 0.0f) ? 1.0f : ((s < 0.0f) ? -1.0f : 0.0f);
    }
}

extern "C" void kernel_launch(void* const* d_in, const int* in_sizes, int n_in,
                              void* d_out, int out_size) {
    const float* adj = (const float*)d_in[0];   // [8192, 8192] fp32 row-major
    const float* x   = (const float*)d_in[1];   // [8192] fp32
    float* out       = (float*)d_out;           // [8192] fp32

    hopfield_fused_kernel<<<N_CITIES / ROWS_PER_BLOCK, THREADS>>>(adj, x, out);
}

// round 17
// speedup vs baseline: 1.0405x; 1.0392x over previous
#include <cuda_runtime.h>
#include <cuda_bf16.h>

// HopfieldTSP — FINAL (best harness time of session: 49.18us, R5 config).
//
// Math: x_1000 = sign(w @ x0). With w = 2*diag(rowsum) - adj (off-diag) and
// adj >= 0 uniform(0,1), x1 = sign(w@x0) is a provable fixed point of
// x <- sign(w@x): for any x with entries in {-1,+1},
//   x_i * (w@x)_i >= 2*rowsum_i - |sum_j adj_ij x_j| >= rowsum_i ~ 4096 > 0,
// margin vastly above fp32 rounding. So 1000 iterations collapse to ONE
// fused pass computing rowsum_i and dot_i = (adj@x0)_i together:
//   s_i = (2*rowsum_i + adj_ii)*x0_i - dot_i ;  out_i = sign(s_i).
//
// Performance: single 268MB read at the chip's effective read ceiling
// (~5.7-5.8TB/s on a fast hold), verified mechanism-independent across LDG
// (all 4 cache-ops), TMA bulk pipelines, and cp.async with 118KB/SM in
// flight (R1-R16). Kernel time ~47.4us vs 46.7us ideal at that ceiling.
// Hold-to-hold board-state noise is +-2.5-3us and exceeds all remaining
// variant differences (verified by two identical-source replications).
//
// Shape: 256-thread blocks, one full row per warp, no barriers/smem;
// adj streamed with __ldcs (evict-first, keeps L1 for x), x via __ldg
// (32KB, L1-resident); grid 1024 = one wave at 8 blocks/SM; 30 regs.

#define N_CITIES 8192
#define THREADS 256
#define ROWS_PER_BLOCK (THREADS / 32)   // 8
#define ROW4 (N_CITIES / 4)             // 2048 float4 per row

__global__ void __launch_bounds__(THREADS, 8)
hopfield_fused_kernel(const float* __restrict__ adj,
                      const float* __restrict__ x,
                      float* __restrict__ out) {
    const int warp = threadIdx.x >> 5;
    const int lane = threadIdx.x & 31;
    const int row  = blockIdx.x * ROWS_PER_BLOCK + warp;

    const float4* arow = reinterpret_cast<const float4*>(adj + (size_t)row * N_CITIES);
    const float4* x4   = reinterpret_cast<const float4*>(x);

    // 64 trips per lane. adj: streaming (evict-first) so it never evicts x
    // from L1; x: read-only path, hot in L1 after first touch.
    float rs = 0.0f, dot = 0.0f;
    #pragma unroll 2
    for (int j = lane; j < ROW4; j += 32) {
        float4 a  = __ldcs(&arow[j]);
        float4 xv = __ldg(&x4[j]);
        rs  += (a.x + a.y) + (a.z + a.w);
        dot += a.x * xv.x + a.y * xv.y + a.z * xv.z + a.w * xv.w;
    }

    #pragma unroll
    for (int o = 16; o > 0; o >>= 1) {
        rs  += __shfl_xor_sync(0xFFFFFFFFu, rs, o);
        dot += __shfl_xor_sync(0xFFFFFFFFu, dot, o);
    }

    if (lane == 0) {
        float aii = __ldg(adj + (size_t)row * N_CITIES + row);
        float xi  = __ldg(x + row);
        float s   = (2.0f * rs + aii) * xi - dot;
        out[row] = (s > 0.0f) ? 1.0f : ((s < 0.0f) ? -1.0f : 0.0f);
    }
}

extern "C" void kernel_launch(void* const* d_in, const int* in_sizes, int n_in,
                              void* d_out, int out_size) {
    const float* adj = (const float*)d_in[0];   // [8192, 8192] fp32 row-major
    const float* x   = (const float*)d_in[1];   // [8192] fp32
    float* out       = (float*)d_out;           // [8192] fp32

    hopfield_fused_kernel<<<N_CITIES / ROWS_PER_BLOCK, THREADS>>>(adj, x, out);
}